// round 15
// baseline (speedup 1.0000x reference)
#include <cuda_runtime.h>
#include <cuda_fp16.h>
#include <cstdint>

// Problem constants
#define TT    2048
#define CIN   256
#define NB    4
#define NHEAD 8
#define DK    64
#define NH    (NB*NHEAD)   // 32

#define BQ    256          // queries per CTA (attention)
#define BK    64           // keys per tile (attention)
#define NKT   (TT/BK)      // 32

// fold (1/sqrt(64)) * log2(e) into Q at projection time
#define QSCALE 0.18033688011112042f

// fp16 copies of inputs (converted once per launch)
__device__ __align__(16) __half g_xh[(size_t)NB * CIN * TT];        // 4 MB
__device__ __align__(16) __half g_wh[(size_t)3 * 512 * CIN];        // 768 KB

// Q/K/V scratch in fp16, [nh][t][d] layout (8 MB each)
__device__ __align__(16) __half g_qh[(size_t)NH * TT * DK];
__device__ __align__(16) __half g_kh[(size_t)NH * TT * DK];
__device__ __align__(16) __half g_vh[(size_t)NH * TT * DK];

// ---------------------------------------------------------------------------
// helpers
// ---------------------------------------------------------------------------
__device__ __forceinline__ uint32_t smem_u32(const void* p) {
    uint32_t a;
    asm("{ .reg .u64 t; cvta.to.shared.u64 t, %1; cvt.u32.u64 %0, t; }" : "=r"(a) : "l"(p));
    return a;
}
__device__ __forceinline__ void cp_async16(uint32_t dst, const void* src) {
    asm volatile("cp.async.cg.shared.global [%0], [%1], 16;" :: "r"(dst), "l"(src));
}
__device__ __forceinline__ void cp_commit() {
    asm volatile("cp.async.commit_group;");
}
__device__ __forceinline__ void ldsm_x4(uint32_t& r0, uint32_t& r1, uint32_t& r2, uint32_t& r3, uint32_t a) {
    asm volatile("ldmatrix.sync.aligned.m8n8.x4.shared.b16 {%0,%1,%2,%3}, [%4];"
                 : "=r"(r0), "=r"(r1), "=r"(r2), "=r"(r3) : "r"(a));
}
__device__ __forceinline__ void ldsm_x4_t(uint32_t& r0, uint32_t& r1, uint32_t& r2, uint32_t& r3, uint32_t a) {
    asm volatile("ldmatrix.sync.aligned.m8n8.x4.trans.shared.b16 {%0,%1,%2,%3}, [%4];"
                 : "=r"(r0), "=r"(r1), "=r"(r2), "=r"(r3) : "r"(a));
}
__device__ __forceinline__ void mma16816(float* c, uint32_t a0, uint32_t a1, uint32_t a2, uint32_t a3,
                                         uint32_t b0, uint32_t b1) {
    asm volatile(
        "mma.sync.aligned.m16n8k16.row.col.f32.f16.f16.f32 "
        "{%0,%1,%2,%3}, {%4,%5,%6,%7}, {%8,%9}, {%0,%1,%2,%3};"
        : "+f"(c[0]), "+f"(c[1]), "+f"(c[2]), "+f"(c[3])
        : "r"(a0), "r"(a1), "r"(a2), "r"(a3), "r"(b0), "r"(b1));
}
__device__ __forceinline__ uint32_t pack_h2(float lo, float hi) {
    uint32_t r;
    asm("cvt.rn.f16x2.f32 %0, %1, %2;" : "=r"(r) : "f"(hi), "f"(lo));
    return r;
}
__device__ __forceinline__ uint32_t exp2_h2(float lo, float hi) {
    uint32_t h = pack_h2(lo, hi);
    uint32_t r;
    asm("ex2.approx.f16x2 %0, %1;" : "=r"(r) : "r"(h));
    return r;
}
__device__ __forceinline__ uint32_t swz(int r, int c) {
    return (uint32_t)r * 128u + (uint32_t)((c ^ (r & 7)) << 4);
}
__device__ __forceinline__ uint32_t swz16(int r, int c) {
    return (uint32_t)r * 256u + (uint32_t)((c ^ (r & 7)) << 4);
}

// ---------------------------------------------------------------------------
// Chunked fp32 -> fp16 conversion: blocks [0,1024) convert 2 batches of x
// starting at n_base; blocks [1024,1408) convert all of W.
// ---------------------------------------------------------------------------
__global__ __launch_bounds__(256) void convert_chunk_kernel(
    const float* __restrict__ x,
    const float* __restrict__ Wq, const float* __restrict__ Wk, const float* __restrict__ Wv,
    int n_base)
{
    if (blockIdx.x < 1024) {
        size_t idx = (size_t)n_base * (CIN * TT / 4) + (size_t)blockIdx.x * 256 + threadIdx.x;
        const float4 f = ((const float4*)x)[idx];
        uint2 u;
        u.x = pack_h2(f.x, f.y);
        u.y = pack_h2(f.z, f.w);
        ((uint2*)g_xh)[idx] = u;
    } else {
        size_t idx = (size_t)(blockIdx.x - 1024) * 256 + threadIdx.x;
        const int w = (int)(idx >> 15);
        const size_t rem = idx & 32767;
        const float* W = (w == 0) ? Wq : (w == 1) ? Wk : Wv;
        const float4 f = ((const float4*)W)[rem];
        uint2 u;
        u.x = pack_h2(f.x, f.y);
        u.y = pack_h2(f.z, f.w);
        ((uint2*)g_wh)[idx] = u;
    }
}

// ---------------------------------------------------------------------------
// Fused tensor-core projection, chunked + DOUBLE-BUFFERED: cp.async for
// block cb+2 overlaps MMA work of block cb (was: 4 exposed DRAM round trips
// per CTA -> now ~1). 2 stages x 56KB = 112KB SMEM.
// grid = (T/128, NHEAD, 2); n = blockIdx.z + n_base.
// ---------------------------------------------------------------------------
#define PSTG      57344
#define PX_OFF(s) ((s) * PSTG)
#define PW_OFF(s,w) ((s) * PSTG + 32768 + (w) * 8192)
#define PROJ_SMEM (2 * PSTG)   // 114688

__global__ __launch_bounds__(256) void proj_tc_kernel(int n_base)
{
    extern __shared__ char psm[];
    const uint32_t su = smem_u32(psm);

    const int tid = threadIdx.x;
    const int wid = tid >> 5;
    const int lid = tid & 31;
    const int g   = lid >> 2;
    const int t4  = lid & 3;

    const int t0 = blockIdx.x * 128;
    const int h  = blockIdx.y;
    const int n  = blockIdx.z + n_base;

    const __half* xb = g_xh + (size_t)n * CIN * TT;

    float C[3][8][4];
    #pragma unroll
    for (int w = 0; w < 3; w++)
        #pragma unroll
        for (int j = 0; j < 8; j++)
            #pragma unroll
            for (int i = 0; i < 4; i++) C[w][j][i] = 0.f;

    // prefetch cb = 0, 1 into stages 0, 1
    #pragma unroll
    for (int pf = 0; pf < 2; pf++) {
        const int c0 = pf * 64;
        #pragma unroll
        for (int l = 0; l < 4; l++) {
            int id = l * 256 + tid;
            int r = id >> 4, ch = id & 15;
            cp_async16(su + PX_OFF(pf) + swz16(r, ch),
                       xb + (size_t)(c0 + r) * TT + t0 + ch * 8);
        }
        #pragma unroll
        for (int l = 0; l < 6; l++) {
            int id = l * 256 + tid;
            int w = id >> 9;
            int within = id & 511;
            int r = within >> 3, ch = within & 7;
            cp_async16(su + PW_OFF(pf, w) + swz(r, ch),
                       g_wh + (size_t)w * 512 * CIN + (size_t)(h * 64 + r) * CIN + c0 + ch * 8);
        }
        cp_commit();
    }

    for (int cb = 0; cb < 4; cb++) {
        if (cb < 3) asm volatile("cp.async.wait_group 1;");
        else        asm volatile("cp.async.wait_group 0;");
        __syncthreads();
        const int sb = cb & 1;

        uint32_t xa[4][4];
        #pragma unroll
        for (int s = 0; s < 4; s++) {
            int row = s * 16 + ((lid & 16) >> 1) + (lid & 7);
            int ch  = wid * 2 + ((lid >> 3) & 1);
            ldsm_x4_t(xa[s][0], xa[s][1], xa[s][2], xa[s][3], su + PX_OFF(sb) + swz16(row, ch));
        }

        #pragma unroll
        for (int w = 0; w < 3; w++) {
            #pragma unroll
            for (int j = 0; j < 8; j++) {
                int rowW = 8 * j + (lid & 7);
                int m = lid >> 3;
                uint32_t b0, b1, b2, b3, b4, b5, b6, b7;
                ldsm_x4(b0, b1, b2, b3, su + PW_OFF(sb, w) + swz(rowW, m));
                ldsm_x4(b4, b5, b6, b7, su + PW_OFF(sb, w) + swz(rowW, m + 4));
                mma16816(C[w][j], xa[0][0], xa[0][1], xa[0][2], xa[0][3], b0, b1);
                mma16816(C[w][j], xa[1][0], xa[1][1], xa[1][2], xa[1][3], b2, b3);
                mma16816(C[w][j], xa[2][0], xa[2][1], xa[2][2], xa[2][3], b4, b5);
                mma16816(C[w][j], xa[3][0], xa[3][1], xa[3][2], xa[3][3], b6, b7);
            }
        }
        __syncthreads();   // all warps done reading stage sb

        if (cb + 2 < 4) {
            const int c0 = (cb + 2) * 64;
            #pragma unroll
            for (int l = 0; l < 4; l++) {
                int id = l * 256 + tid;
                int r = id >> 4, ch = id & 15;
                cp_async16(su + PX_OFF(sb) + swz16(r, ch),
                           xb + (size_t)(c0 + r) * TT + t0 + ch * 8);
            }
            #pragma unroll
            for (int l = 0; l < 6; l++) {
                int id = l * 256 + tid;
                int w = id >> 9;
                int within = id & 511;
                int r = within >> 3, ch = within & 7;
                cp_async16(su + PW_OFF(sb, w) + swz(r, ch),
                           g_wh + (size_t)w * 512 * CIN + (size_t)(h * 64 + r) * CIN + c0 + ch * 8);
            }
            cp_commit();
        }
    }

    const int nh = n * NHEAD + h;
    const int tq = t0 + wid * 16 + g;
    #pragma unroll
    for (int w = 0; w < 3; w++) {
        __half* outp = (w == 0) ? g_qh : (w == 1) ? g_kh : g_vh;
        const float s = (w == 0) ? QSCALE : 1.0f;
        __half* ob = outp + ((size_t)nh * TT + tq) * DK;
        #pragma unroll
        for (int j = 0; j < 8; j++) {
            int d0 = 8 * j + 2 * t4;
            *(__half2*)(ob + d0)          = __floats2half2_rn(C[w][j][0] * s, C[w][j][1] * s);
            *(__half2*)(ob + 8 * DK + d0) = __floats2half2_rn(C[w][j][2] * s, C[w][j][3] * s);
        }
    }
}

// ---------------------------------------------------------------------------
// FlashAttention mma.sync kernel — exact R12/R14 version (best measured).
// ---------------------------------------------------------------------------
#define NSTAGE 4
#define SQ_OFF  0
#define SQ_BYTES (BQ * 128)                    // 32768
#define ST_OFF(s) (SQ_BYTES + (s) * 16384)     // K at +0 (8KB), V at +8192
#define SMEM_BYTES (SQ_BYTES + 16384 * NSTAGE) // 98304

__global__ __launch_bounds__(256, 1) void attn_mma_kernel(float* __restrict__ out, int nh_base)
{
    extern __shared__ char smem[];
    const uint32_t su = smem_u32(smem);
    const int tid = threadIdx.x;
    const int wid = tid >> 5;
    const int lid = tid & 31;
    const int g   = lid >> 2;
    const int t4  = lid & 3;
    const int nh  = blockIdx.y + nh_base;
    const int q0  = blockIdx.x * BQ;

    const __half* qg = g_qh + ((size_t)nh * TT + q0) * DK;
    const __half* kg = g_kh + (size_t)nh * TT * DK;
    const __half* vg = g_vh + (size_t)nh * TT * DK;

    #pragma unroll
    for (int l = 0; l < 8; l++) {
        int id = l * 256 + tid;
        int r = id >> 3, c = id & 7;
        *(uint4*)(smem + SQ_OFF + swz(r, c)) =
            *(const uint4*)(qg + (size_t)r * DK + c * 8);
    }

    #pragma unroll
    for (int pf = 0; pf < NSTAGE - 1; pf++) {
        #pragma unroll
        for (int l = 0; l < 2; l++) {
            int id = l * 256 + tid;
            int r = id >> 3, c = id & 7;
            const size_t go = (size_t)(pf * BK + r) * DK + c * 8;
            cp_async16(su + ST_OFF(pf) + swz(r, c), kg + go);
            cp_async16(su + ST_OFF(pf) + 8192 + swz(r, c), vg + go);
        }
        cp_commit();
    }
    __syncthreads();

    uint32_t qa[2][4][4];
    #pragma unroll
    for (int b = 0; b < 2; b++) {
        #pragma unroll
        for (int s = 0; s < 4; s++) {
            int mm = lid >> 3, r8 = lid & 7;
            int row = wid * 32 + b * 16 + (mm & 1) * 8 + r8;
            int ch  = 2 * s + (mm >> 1);
            ldsm_x4(qa[b][s][0], qa[b][s][1], qa[b][s][2], qa[b][s][3],
                    su + SQ_OFF + swz(row, ch));
        }
    }

    const uint32_t bone = (lid < 4) ? 0x3C003C00u : 0u;

    float O[2][8][4];
    #pragma unroll
    for (int b = 0; b < 2; b++)
        #pragma unroll
        for (int j = 0; j < 8; j++)
            #pragma unroll
            for (int i = 0; i < 4; i++) O[b][j][i] = 0.f;
    float L[2][4];
    #pragma unroll
    for (int b = 0; b < 2; b++)
        #pragma unroll
        for (int i = 0; i < 4; i++) L[b][i] = 0.f;

    for (int it = 0; it < NKT; it++) {
        if (it < NKT - 2)       asm volatile("cp.async.wait_group 2;");
        else if (it == NKT - 2) asm volatile("cp.async.wait_group 1;");
        else                    asm volatile("cp.async.wait_group 0;");
        __syncthreads();

        if (it + NSTAGE - 1 < NKT) {
            const int ps = (it + NSTAGE - 1) & (NSTAGE - 1);
            #pragma unroll
            for (int l = 0; l < 2; l++) {
                int id = l * 256 + tid;
                int r = id >> 3, c = id & 7;
                const size_t go = (size_t)((it + NSTAGE - 1) * BK + r) * DK + c * 8;
                cp_async16(su + ST_OFF(ps) + swz(r, c), kg + go);
                cp_async16(su + ST_OFF(ps) + 8192 + swz(r, c), vg + go);
            }
            cp_commit();
        }

        const uint32_t kb = su + ST_OFF(it & (NSTAGE - 1));
        const uint32_t vb = kb + 8192;
        const int m = lid >> 3, r8 = lid & 7;

        // ---- GEMM1 half 0 ----
        float C0[2][4][4];
        #pragma unroll
        for (int jj = 0; jj < 4; jj++) {
            int row = 8 * jj + r8;
            uint32_t b0, b1, b2, b3, b4, b5, b6, b7;
            ldsm_x4(b0, b1, b2, b3, kb + swz(row, m));
            ldsm_x4(b4, b5, b6, b7, kb + swz(row, m + 4));
            #pragma unroll
            for (int b = 0; b < 2; b++) {
                #pragma unroll
                for (int i = 0; i < 4; i++) C0[b][jj][i] = 0.f;
                mma16816(C0[b][jj], qa[b][0][0], qa[b][0][1], qa[b][0][2], qa[b][0][3], b0, b1);
                mma16816(C0[b][jj], qa[b][1][0], qa[b][1][1], qa[b][1][2], qa[b][1][3], b2, b3);
                mma16816(C0[b][jj], qa[b][2][0], qa[b][2][1], qa[b][2][2], qa[b][2][3], b4, b5);
                mma16816(C0[b][jj], qa[b][3][0], qa[b][3][1], qa[b][3][2], qa[b][3][3], b6, b7);
            }
        }

        // ---- exp half 0 ----
        uint32_t pa0[2][4][2];
        #pragma unroll
        for (int b = 0; b < 2; b++)
            #pragma unroll
            for (int jj = 0; jj < 4; jj++) {
                pa0[b][jj][0] = exp2_h2(C0[b][jj][0], C0[b][jj][1]);
                pa0[b][jj][1] = exp2_h2(C0[b][jj][2], C0[b][jj][3]);
            }

        // ---- GEMM1 half 1 ----
        float C1[2][4][4];
        #pragma unroll
        for (int jj = 0; jj < 4; jj++) {
            int row = 32 + 8 * jj + r8;
            uint32_t b0, b1, b2, b3, b4, b5, b6, b7;
            ldsm_x4(b0, b1, b2, b3, kb + swz(row, m));
            ldsm_x4(b4, b5, b6, b7, kb + swz(row, m + 4));
            #pragma unroll
            for (int b = 0; b < 2; b++) {
                #pragma unroll
                for (int i = 0; i < 4; i++) C1[b][jj][i] = 0.f;
                mma16816(C1[b][jj], qa[b][0][0], qa[b][0][1], qa[b][0][2], qa[b][0][3], b0, b1);
                mma16816(C1[b][jj], qa[b][1][0], qa[b][1][1], qa[b][1][2], qa[b][1][3], b2, b3);
                mma16816(C1[b][jj], qa[b][2][0], qa[b][2][1], qa[b][2][2], qa[b][2][3], b4, b5);
                mma16816(C1[b][jj], qa[b][3][0], qa[b][3][1], qa[b][3][2], qa[b][3][3], b6, b7);
            }
        }

        // ---- L + GEMM2 half 0 ----
        #pragma unroll
        for (int b = 0; b < 2; b++) {
            mma16816(L[b], pa0[b][0][0], pa0[b][0][1], pa0[b][1][0], pa0[b][1][1], bone, bone);
            mma16816(L[b], pa0[b][2][0], pa0[b][2][1], pa0[b][3][0], pa0[b][3][1], bone, bone);
        }
        #pragma unroll
        for (int dj = 0; dj < 8; dj++) {
            uint32_t b0, b1, b2, b3;
            ldsm_x4_t(b0, b1, b2, b3, vb + swz(lid, dj));
            #pragma unroll
            for (int b = 0; b < 2; b++) {
                mma16816(O[b][dj], pa0[b][0][0], pa0[b][0][1], pa0[b][1][0], pa0[b][1][1], b0, b1);
                mma16816(O[b][dj], pa0[b][2][0], pa0[b][2][1], pa0[b][3][0], pa0[b][3][1], b2, b3);
            }
        }

        // ---- exp half 1 ----
        uint32_t pa1[2][4][2];
        #pragma unroll
        for (int b = 0; b < 2; b++)
            #pragma unroll
            for (int jj = 0; jj < 4; jj++) {
                pa1[b][jj][0] = exp2_h2(C1[b][jj][0], C1[b][jj][1]);
                pa1[b][jj][1] = exp2_h2(C1[b][jj][2], C1[b][jj][3]);
            }

        // ---- L + GEMM2 half 1 ----
        #pragma unroll
        for (int b = 0; b < 2; b++) {
            mma16816(L[b], pa1[b][0][0], pa1[b][0][1], pa1[b][1][0], pa1[b][1][1], bone, bone);
            mma16816(L[b], pa1[b][2][0], pa1[b][2][1], pa1[b][3][0], pa1[b][3][1], bone, bone);
        }
        #pragma unroll
        for (int dj = 0; dj < 8; dj++) {
            uint32_t b0, b1, b2, b3;
            ldsm_x4_t(b0, b1, b2, b3, vb + swz(32 + lid, dj));
            #pragma unroll
            for (int b = 0; b < 2; b++) {
                mma16816(O[b][dj], pa1[b][0][0], pa1[b][0][1], pa1[b][1][0], pa1[b][1][1], b0, b1);
                mma16816(O[b][dj], pa1[b][2][0], pa1[b][2][1], pa1[b][3][0], pa1[b][3][1], b2, b3);
            }
        }
    }

    // normalize + store
    float* obase = out + (size_t)nh * DK * TT;
    #pragma unroll
    for (int b = 0; b < 2; b++) {
        const float inv0 = 1.0f / __shfl_sync(0xffffffffu, L[b][0], lid & 28);
        const float inv1 = 1.0f / __shfl_sync(0xffffffffu, L[b][2], lid & 28);
        const int tq = q0 + wid * 32 + b * 16 + g;
        #pragma unroll
        for (int j = 0; j < 8; j++) {
            int d0 = 8 * j + 2 * t4;
            obase[(size_t)d0 * TT + tq]           = O[b][j][0] * inv0;
            obase[(size_t)(d0 + 1) * TT + tq]     = O[b][j][1] * inv0;
            obase[(size_t)d0 * TT + tq + 8]       = O[b][j][2] * inv1;
            obase[(size_t)(d0 + 1) * TT + tq + 8] = O[b][j][3] * inv1;
        }
    }
}

// ---------------------------------------------------------------------------
// Launch: same DAG as R14 (best), proj now double-buffered.
//   s0: convX(0,1)+W -> proj(0,1) -> attn(nh 0..15) -> wait -> attn(16..31)
//   s2: convX(2,3) [from t=0] -> wait W -> proj(2,3)
// ---------------------------------------------------------------------------
extern "C" void kernel_launch(void* const* d_in, const int* in_sizes, int n_in,
                              void* d_out, int out_size)
{
    const float* x  = (const float*)d_in[0];
    const float* Wq = (const float*)d_in[1];
    const float* Wk = (const float*)d_in[2];
    const float* Wv = (const float*)d_in[3];
    float* out = (float*)d_out;

    cudaFuncSetAttribute(proj_tc_kernel,
                         cudaFuncAttributeMaxDynamicSharedMemorySize, PROJ_SMEM);
    cudaFuncSetAttribute(attn_mma_kernel,
                         cudaFuncAttributeMaxDynamicSharedMemorySize, SMEM_BYTES);

    cudaStream_t s2;
    cudaStreamCreateWithFlags(&s2, cudaStreamNonBlocking);
    cudaEvent_t evW, evStart, evJoin;
    cudaEventCreateWithFlags(&evW, cudaEventDisableTiming);
    cudaEventCreateWithFlags(&evStart, cudaEventDisableTiming);
    cudaEventCreateWithFlags(&evJoin, cudaEventDisableTiming);

    dim3 pgrid(TT / 128, NHEAD, 2);
    dim3 agrid(TT / BQ, NH / 2);

    cudaEventRecord(evStart, 0);
    cudaStreamWaitEvent(s2, evStart, 0);

    // s2: convert x batches 2,3
    convert_chunk_kernel<<<1024, 256, 0, s2>>>(x, Wq, Wk, Wv, 2);

    // s0: convert x batches 0,1 + all W
    convert_chunk_kernel<<<1408, 256>>>(x, Wq, Wk, Wv, 0);
    cudaEventRecord(evW, 0);

    // s0: proj batches 0,1
    proj_tc_kernel<<<pgrid, 256, PROJ_SMEM>>>(0);

    // s2: proj batches 2,3 (needs W)
    cudaStreamWaitEvent(s2, evW, 0);
    proj_tc_kernel<<<pgrid, 256, PROJ_SMEM, s2>>>(2);
    cudaEventRecord(evJoin, s2);

    // s0: attn chunk 0
    attn_mma_kernel<<<agrid, 256, SMEM_BYTES>>>(out, 0);

    // join, then attn chunk 1
    cudaStreamWaitEvent(0, evJoin, 0);
    attn_mma_kernel<<<agrid, 256, SMEM_BYTES>>>(out, NH / 2);
}

// round 16
// speedup vs baseline: 1.0301x; 1.0301x over previous
#include <cuda_runtime.h>
#include <cuda_fp16.h>
#include <cstdint>

// Problem constants
#define TT    2048
#define CIN   256
#define NB    4
#define NHEAD 8
#define DK    64
#define NH    (NB*NHEAD)   // 32

#define BQ    256          // queries per CTA (attention)
#define BK    64           // keys per tile (attention)
#define NKT   (TT/BK)      // 32

// fold (1/sqrt(64)) * log2(e) into Q at projection time
#define QSCALE 0.18033688011112042f

// fp16 copies of inputs (converted once per launch)
__device__ __align__(16) __half g_xh[(size_t)NB * CIN * TT];        // 4 MB
__device__ __align__(16) __half g_wh[(size_t)3 * 512 * CIN];        // 768 KB

// Q/K/V scratch in fp16, [nh][t][d] layout (8 MB each)
__device__ __align__(16) __half g_qh[(size_t)NH * TT * DK];
__device__ __align__(16) __half g_kh[(size_t)NH * TT * DK];
__device__ __align__(16) __half g_vh[(size_t)NH * TT * DK];

// ---------------------------------------------------------------------------
// helpers
// ---------------------------------------------------------------------------
__device__ __forceinline__ uint32_t smem_u32(const void* p) {
    uint32_t a;
    asm("{ .reg .u64 t; cvta.to.shared.u64 t, %1; cvt.u32.u64 %0, t; }" : "=r"(a) : "l"(p));
    return a;
}
__device__ __forceinline__ void cp_async16(uint32_t dst, const void* src) {
    asm volatile("cp.async.cg.shared.global [%0], [%1], 16;" :: "r"(dst), "l"(src));
}
__device__ __forceinline__ void cp_commit() {
    asm volatile("cp.async.commit_group;");
}
__device__ __forceinline__ void ldsm_x4(uint32_t& r0, uint32_t& r1, uint32_t& r2, uint32_t& r3, uint32_t a) {
    asm volatile("ldmatrix.sync.aligned.m8n8.x4.shared.b16 {%0,%1,%2,%3}, [%4];"
                 : "=r"(r0), "=r"(r1), "=r"(r2), "=r"(r3) : "r"(a));
}
__device__ __forceinline__ void ldsm_x4_t(uint32_t& r0, uint32_t& r1, uint32_t& r2, uint32_t& r3, uint32_t a) {
    asm volatile("ldmatrix.sync.aligned.m8n8.x4.trans.shared.b16 {%0,%1,%2,%3}, [%4];"
                 : "=r"(r0), "=r"(r1), "=r"(r2), "=r"(r3) : "r"(a));
}
__device__ __forceinline__ void mma16816(float* c, uint32_t a0, uint32_t a1, uint32_t a2, uint32_t a3,
                                         uint32_t b0, uint32_t b1) {
    asm volatile(
        "mma.sync.aligned.m16n8k16.row.col.f32.f16.f16.f32 "
        "{%0,%1,%2,%3}, {%4,%5,%6,%7}, {%8,%9}, {%0,%1,%2,%3};"
        : "+f"(c[0]), "+f"(c[1]), "+f"(c[2]), "+f"(c[3])
        : "r"(a0), "r"(a1), "r"(a2), "r"(a3), "r"(b0), "r"(b1));
}
__device__ __forceinline__ uint32_t pack_h2(float lo, float hi) {
    uint32_t r;
    asm("cvt.rn.f16x2.f32 %0, %1, %2;" : "=r"(r) : "f"(hi), "f"(lo));
    return r;
}
__device__ __forceinline__ uint32_t exp2_h2(float lo, float hi) {
    uint32_t h = pack_h2(lo, hi);
    uint32_t r;
    asm("ex2.approx.f16x2 %0, %1;" : "=r"(r) : "r"(h));
    return r;
}
__device__ __forceinline__ uint32_t swz(int r, int c) {
    return (uint32_t)r * 128u + (uint32_t)((c ^ (r & 7)) << 4);
}
__device__ __forceinline__ uint32_t swz16(int r, int c) {
    return (uint32_t)r * 256u + (uint32_t)((c ^ (r & 7)) << 4);
}

// ---------------------------------------------------------------------------
// Chunked fp32 -> fp16 conversion: blocks [0,1024) convert 2 batches of x
// starting at n_base; blocks [1024,1408) convert all of W.
// ---------------------------------------------------------------------------
__global__ __launch_bounds__(256) void convert_chunk_kernel(
    const float* __restrict__ x,
    const float* __restrict__ Wq, const float* __restrict__ Wk, const float* __restrict__ Wv,
    int n_base)
{
    if (blockIdx.x < 1024) {
        size_t idx = (size_t)n_base * (CIN * TT / 4) + (size_t)blockIdx.x * 256 + threadIdx.x;
        const float4 f = ((const float4*)x)[idx];
        uint2 u;
        u.x = pack_h2(f.x, f.y);
        u.y = pack_h2(f.z, f.w);
        ((uint2*)g_xh)[idx] = u;
    } else {
        size_t idx = (size_t)(blockIdx.x - 1024) * 256 + threadIdx.x;
        const int w = (int)(idx >> 15);
        const size_t rem = idx & 32767;
        const float* W = (w == 0) ? Wq : (w == 1) ? Wk : Wv;
        const float4 f = ((const float4*)W)[rem];
        uint2 u;
        u.x = pack_h2(f.x, f.y);
        u.y = pack_h2(f.z, f.w);
        ((uint2*)g_wh)[idx] = u;
    }
}

// ---------------------------------------------------------------------------
// Tensor-core projection, v4: ONE weight matrix per CTA (w in grid.z) so
// per-CTA registers (C: 96->32) and SMEM (56->40KB/stage) drop enough for
// 2 CTAs/SM (launch_bounds(256,2) -> 128-reg cap, 4 warps/SMSP). Double-
// buffered cb staging. grid = (T/128, NHEAD, 6): z -> (w, n-n_base).
// ---------------------------------------------------------------------------
#define PSTG      40960
#define PX_OFF(s) ((s) * PSTG)
#define PW_OFF(s) ((s) * PSTG + 32768)
#define PROJ_SMEM (2 * PSTG)   // 81920

__global__ __launch_bounds__(256, 2) void proj_tc_kernel(int n_base)
{
    extern __shared__ char psm[];
    const uint32_t su = smem_u32(psm);

    const int tid = threadIdx.x;
    const int wid = tid >> 5;
    const int lid = tid & 31;
    const int g   = lid >> 2;
    const int t4  = lid & 3;

    const int t0 = blockIdx.x * 128;
    const int h  = blockIdx.y;
    const int w  = blockIdx.z >> 1;                 // 0=q,1=k,2=v
    const int n  = n_base + (blockIdx.z & 1);

    const __half* xb = g_xh + (size_t)n * CIN * TT;
    const __half* Wb = g_wh + (size_t)w * 512 * CIN + (size_t)h * 64 * CIN;

    float C[8][4];
    #pragma unroll
    for (int j = 0; j < 8; j++)
        #pragma unroll
        for (int i = 0; i < 4; i++) C[j][i] = 0.f;

    // prefetch cb = 0, 1 into stages 0, 1
    #pragma unroll
    for (int pf = 0; pf < 2; pf++) {
        const int c0 = pf * 64;
        #pragma unroll
        for (int l = 0; l < 4; l++) {
            int id = l * 256 + tid;
            int r = id >> 4, ch = id & 15;
            cp_async16(su + PX_OFF(pf) + swz16(r, ch),
                       xb + (size_t)(c0 + r) * TT + t0 + ch * 8);
        }
        #pragma unroll
        for (int l = 0; l < 2; l++) {
            int id = l * 256 + tid;
            int r = id >> 3, ch = id & 7;
            cp_async16(su + PW_OFF(pf) + swz(r, ch),
                       Wb + (size_t)r * CIN + c0 + ch * 8);
        }
        cp_commit();
    }

    for (int cb = 0; cb < 4; cb++) {
        if (cb < 3) asm volatile("cp.async.wait_group 1;");
        else        asm volatile("cp.async.wait_group 0;");
        __syncthreads();
        const int sb = cb & 1;

        uint32_t xa[4][4];
        #pragma unroll
        for (int s = 0; s < 4; s++) {
            int row = s * 16 + ((lid & 16) >> 1) + (lid & 7);
            int ch  = wid * 2 + ((lid >> 3) & 1);
            ldsm_x4_t(xa[s][0], xa[s][1], xa[s][2], xa[s][3], su + PX_OFF(sb) + swz16(row, ch));
        }

        #pragma unroll
        for (int j = 0; j < 8; j++) {
            int rowW = 8 * j + (lid & 7);
            int m = lid >> 3;
            uint32_t b0, b1, b2, b3, b4, b5, b6, b7;
            ldsm_x4(b0, b1, b2, b3, su + PW_OFF(sb) + swz(rowW, m));
            ldsm_x4(b4, b5, b6, b7, su + PW_OFF(sb) + swz(rowW, m + 4));
            mma16816(C[j], xa[0][0], xa[0][1], xa[0][2], xa[0][3], b0, b1);
            mma16816(C[j], xa[1][0], xa[1][1], xa[1][2], xa[1][3], b2, b3);
            mma16816(C[j], xa[2][0], xa[2][1], xa[2][2], xa[2][3], b4, b5);
            mma16816(C[j], xa[3][0], xa[3][1], xa[3][2], xa[3][3], b6, b7);
        }
        __syncthreads();   // all warps done reading stage sb

        if (cb + 2 < 4) {
            const int c0 = (cb + 2) * 64;
            #pragma unroll
            for (int l = 0; l < 4; l++) {
                int id = l * 256 + tid;
                int r = id >> 4, ch = id & 15;
                cp_async16(su + PX_OFF(sb) + swz16(r, ch),
                           xb + (size_t)(c0 + r) * TT + t0 + ch * 8);
            }
            #pragma unroll
            for (int l = 0; l < 2; l++) {
                int id = l * 256 + tid;
                int r = id >> 3, ch = id & 7;
                cp_async16(su + PW_OFF(sb) + swz(r, ch),
                           Wb + (size_t)r * CIN + c0 + ch * 8);
            }
            cp_commit();
        }
    }

    const int nh = n * NHEAD + h;
    const int tq = t0 + wid * 16 + g;
    __half* outp = (w == 0) ? g_qh : (w == 1) ? g_kh : g_vh;
    const float s = (w == 0) ? QSCALE : 1.0f;
    __half* ob = outp + ((size_t)nh * TT + tq) * DK;
    #pragma unroll
    for (int j = 0; j < 8; j++) {
        int d0 = 8 * j + 2 * t4;
        *(__half2*)(ob + d0)          = __floats2half2_rn(C[j][0] * s, C[j][1] * s);
        *(__half2*)(ob + 8 * DK + d0) = __floats2half2_rn(C[j][2] * s, C[j][3] * s);
    }
}

// ---------------------------------------------------------------------------
// FlashAttention mma.sync kernel — exact R12/R14 version (best measured).
// ---------------------------------------------------------------------------
#define NSTAGE 4
#define SQ_OFF  0
#define SQ_BYTES (BQ * 128)                    // 32768
#define ST_OFF(s) (SQ_BYTES + (s) * 16384)     // K at +0 (8KB), V at +8192
#define SMEM_BYTES (SQ_BYTES + 16384 * NSTAGE) // 98304

__global__ __launch_bounds__(256, 1) void attn_mma_kernel(float* __restrict__ out, int nh_base)
{
    extern __shared__ char smem[];
    const uint32_t su = smem_u32(smem);
    const int tid = threadIdx.x;
    const int wid = tid >> 5;
    const int lid = tid & 31;
    const int g   = lid >> 2;
    const int t4  = lid & 3;
    const int nh  = blockIdx.y + nh_base;
    const int q0  = blockIdx.x * BQ;

    const __half* qg = g_qh + ((size_t)nh * TT + q0) * DK;
    const __half* kg = g_kh + (size_t)nh * TT * DK;
    const __half* vg = g_vh + (size_t)nh * TT * DK;

    #pragma unroll
    for (int l = 0; l < 8; l++) {
        int id = l * 256 + tid;
        int r = id >> 3, c = id & 7;
        *(uint4*)(smem + SQ_OFF + swz(r, c)) =
            *(const uint4*)(qg + (size_t)r * DK + c * 8);
    }

    #pragma unroll
    for (int pf = 0; pf < NSTAGE - 1; pf++) {
        #pragma unroll
        for (int l = 0; l < 2; l++) {
            int id = l * 256 + tid;
            int r = id >> 3, c = id & 7;
            const size_t go = (size_t)(pf * BK + r) * DK + c * 8;
            cp_async16(su + ST_OFF(pf) + swz(r, c), kg + go);
            cp_async16(su + ST_OFF(pf) + 8192 + swz(r, c), vg + go);
        }
        cp_commit();
    }
    __syncthreads();

    uint32_t qa[2][4][4];
    #pragma unroll
    for (int b = 0; b < 2; b++) {
        #pragma unroll
        for (int s = 0; s < 4; s++) {
            int mm = lid >> 3, r8 = lid & 7;
            int row = wid * 32 + b * 16 + (mm & 1) * 8 + r8;
            int ch  = 2 * s + (mm >> 1);
            ldsm_x4(qa[b][s][0], qa[b][s][1], qa[b][s][2], qa[b][s][3],
                    su + SQ_OFF + swz(row, ch));
        }
    }

    const uint32_t bone = (lid < 4) ? 0x3C003C00u : 0u;

    float O[2][8][4];
    #pragma unroll
    for (int b = 0; b < 2; b++)
        #pragma unroll
        for (int j = 0; j < 8; j++)
            #pragma unroll
            for (int i = 0; i < 4; i++) O[b][j][i] = 0.f;
    float L[2][4];
    #pragma unroll
    for (int b = 0; b < 2; b++)
        #pragma unroll
        for (int i = 0; i < 4; i++) L[b][i] = 0.f;

    for (int it = 0; it < NKT; it++) {
        if (it < NKT - 2)       asm volatile("cp.async.wait_group 2;");
        else if (it == NKT - 2) asm volatile("cp.async.wait_group 1;");
        else                    asm volatile("cp.async.wait_group 0;");
        __syncthreads();

        if (it + NSTAGE - 1 < NKT) {
            const int ps = (it + NSTAGE - 1) & (NSTAGE - 1);
            #pragma unroll
            for (int l = 0; l < 2; l++) {
                int id = l * 256 + tid;
                int r = id >> 3, c = id & 7;
                const size_t go = (size_t)((it + NSTAGE - 1) * BK + r) * DK + c * 8;
                cp_async16(su + ST_OFF(ps) + swz(r, c), kg + go);
                cp_async16(su + ST_OFF(ps) + 8192 + swz(r, c), vg + go);
            }
            cp_commit();
        }

        const uint32_t kb = su + ST_OFF(it & (NSTAGE - 1));
        const uint32_t vb = kb + 8192;
        const int m = lid >> 3, r8 = lid & 7;

        // ---- GEMM1 half 0 ----
        float C0[2][4][4];
        #pragma unroll
        for (int jj = 0; jj < 4; jj++) {
            int row = 8 * jj + r8;
            uint32_t b0, b1, b2, b3, b4, b5, b6, b7;
            ldsm_x4(b0, b1, b2, b3, kb + swz(row, m));
            ldsm_x4(b4, b5, b6, b7, kb + swz(row, m + 4));
            #pragma unroll
            for (int b = 0; b < 2; b++) {
                #pragma unroll
                for (int i = 0; i < 4; i++) C0[b][jj][i] = 0.f;
                mma16816(C0[b][jj], qa[b][0][0], qa[b][0][1], qa[b][0][2], qa[b][0][3], b0, b1);
                mma16816(C0[b][jj], qa[b][1][0], qa[b][1][1], qa[b][1][2], qa[b][1][3], b2, b3);
                mma16816(C0[b][jj], qa[b][2][0], qa[b][2][1], qa[b][2][2], qa[b][2][3], b4, b5);
                mma16816(C0[b][jj], qa[b][3][0], qa[b][3][1], qa[b][3][2], qa[b][3][3], b6, b7);
            }
        }

        // ---- exp half 0 ----
        uint32_t pa0[2][4][2];
        #pragma unroll
        for (int b = 0; b < 2; b++)
            #pragma unroll
            for (int jj = 0; jj < 4; jj++) {
                pa0[b][jj][0] = exp2_h2(C0[b][jj][0], C0[b][jj][1]);
                pa0[b][jj][1] = exp2_h2(C0[b][jj][2], C0[b][jj][3]);
            }

        // ---- GEMM1 half 1 ----
        float C1[2][4][4];
        #pragma unroll
        for (int jj = 0; jj < 4; jj++) {
            int row = 32 + 8 * jj + r8;
            uint32_t b0, b1, b2, b3, b4, b5, b6, b7;
            ldsm_x4(b0, b1, b2, b3, kb + swz(row, m));
            ldsm_x4(b4, b5, b6, b7, kb + swz(row, m + 4));
            #pragma unroll
            for (int b = 0; b < 2; b++) {
                #pragma unroll
                for (int i = 0; i < 4; i++) C1[b][jj][i] = 0.f;
                mma16816(C1[b][jj], qa[b][0][0], qa[b][0][1], qa[b][0][2], qa[b][0][3], b0, b1);
                mma16816(C1[b][jj], qa[b][1][0], qa[b][1][1], qa[b][1][2], qa[b][1][3], b2, b3);
                mma16816(C1[b][jj], qa[b][2][0], qa[b][2][1], qa[b][2][2], qa[b][2][3], b4, b5);
                mma16816(C1[b][jj], qa[b][3][0], qa[b][3][1], qa[b][3][2], qa[b][3][3], b6, b7);
            }
        }

        // ---- L + GEMM2 half 0 ----
        #pragma unroll
        for (int b = 0; b < 2; b++) {
            mma16816(L[b], pa0[b][0][0], pa0[b][0][1], pa0[b][1][0], pa0[b][1][1], bone, bone);
            mma16816(L[b], pa0[b][2][0], pa0[b][2][1], pa0[b][3][0], pa0[b][3][1], bone, bone);
        }
        #pragma unroll
        for (int dj = 0; dj < 8; dj++) {
            uint32_t b0, b1, b2, b3;
            ldsm_x4_t(b0, b1, b2, b3, vb + swz(lid, dj));
            #pragma unroll
            for (int b = 0; b < 2; b++) {
                mma16816(O[b][dj], pa0[b][0][0], pa0[b][0][1], pa0[b][1][0], pa0[b][1][1], b0, b1);
                mma16816(O[b][dj], pa0[b][2][0], pa0[b][2][1], pa0[b][3][0], pa0[b][3][1], b2, b3);
            }
        }

        // ---- exp half 1 ----
        uint32_t pa1[2][4][2];
        #pragma unroll
        for (int b = 0; b < 2; b++)
            #pragma unroll
            for (int jj = 0; jj < 4; jj++) {
                pa1[b][jj][0] = exp2_h2(C1[b][jj][0], C1[b][jj][1]);
                pa1[b][jj][1] = exp2_h2(C1[b][jj][2], C1[b][jj][3]);
            }

        // ---- L + GEMM2 half 1 ----
        #pragma unroll
        for (int b = 0; b < 2; b++) {
            mma16816(L[b], pa1[b][0][0], pa1[b][0][1], pa1[b][1][0], pa1[b][1][1], bone, bone);
            mma16816(L[b], pa1[b][2][0], pa1[b][2][1], pa1[b][3][0], pa1[b][3][1], bone, bone);
        }
        #pragma unroll
        for (int dj = 0; dj < 8; dj++) {
            uint32_t b0, b1, b2, b3;
            ldsm_x4_t(b0, b1, b2, b3, vb + swz(32 + lid, dj));
            #pragma unroll
            for (int b = 0; b < 2; b++) {
                mma16816(O[b][dj], pa1[b][0][0], pa1[b][0][1], pa1[b][1][0], pa1[b][1][1], b0, b1);
                mma16816(O[b][dj], pa1[b][2][0], pa1[b][2][1], pa1[b][3][0], pa1[b][3][1], b2, b3);
            }
        }
    }

    // normalize + store
    float* obase = out + (size_t)nh * DK * TT;
    #pragma unroll
    for (int b = 0; b < 2; b++) {
        const float inv0 = 1.0f / __shfl_sync(0xffffffffu, L[b][0], lid & 28);
        const float inv1 = 1.0f / __shfl_sync(0xffffffffu, L[b][2], lid & 28);
        const int tq = q0 + wid * 32 + b * 16 + g;
        #pragma unroll
        for (int j = 0; j < 8; j++) {
            int d0 = 8 * j + 2 * t4;
            obase[(size_t)d0 * TT + tq]           = O[b][j][0] * inv0;
            obase[(size_t)(d0 + 1) * TT + tq]     = O[b][j][1] * inv0;
            obase[(size_t)d0 * TT + tq + 8]       = O[b][j][2] * inv1;
            obase[(size_t)(d0 + 1) * TT + tq + 8] = O[b][j][3] * inv1;
        }
    }
}

// ---------------------------------------------------------------------------
// Launch: same DAG as R14/R15 (best); proj now split by weight matrix.
//   s0: convX(0,1)+W -> proj(0,1) -> attn(nh 0..15) -> wait -> attn(16..31)
//   s2: convX(2,3) [from t=0] -> wait W -> proj(2,3)
// ---------------------------------------------------------------------------
extern "C" void kernel_launch(void* const* d_in, const int* in_sizes, int n_in,
                              void* d_out, int out_size)
{
    const float* x  = (const float*)d_in[0];
    const float* Wq = (const float*)d_in[1];
    const float* Wk = (const float*)d_in[2];
    const float* Wv = (const float*)d_in[3];
    float* out = (float*)d_out;

    cudaFuncSetAttribute(proj_tc_kernel,
                         cudaFuncAttributeMaxDynamicSharedMemorySize, PROJ_SMEM);
    cudaFuncSetAttribute(attn_mma_kernel,
                         cudaFuncAttributeMaxDynamicSharedMemorySize, SMEM_BYTES);

    cudaStream_t s2;
    cudaStreamCreateWithFlags(&s2, cudaStreamNonBlocking);
    cudaEvent_t evW, evStart, evJoin;
    cudaEventCreateWithFlags(&evW, cudaEventDisableTiming);
    cudaEventCreateWithFlags(&evStart, cudaEventDisableTiming);
    cudaEventCreateWithFlags(&evJoin, cudaEventDisableTiming);

    dim3 pgrid(TT / 128, NHEAD, 6);   // z = (w, n-n_base)
    dim3 agrid(TT / BQ, NH / 2);

    cudaEventRecord(evStart, 0);
    cudaStreamWaitEvent(s2, evStart, 0);

    // s2: convert x batches 2,3
    convert_chunk_kernel<<<1024, 256, 0, s2>>>(x, Wq, Wk, Wv, 2);

    // s0: convert x batches 0,1 + all W
    convert_chunk_kernel<<<1408, 256>>>(x, Wq, Wk, Wv, 0);
    cudaEventRecord(evW, 0);

    // s0: proj batches 0,1 (q,k,v split across grid.z)
    proj_tc_kernel<<<pgrid, 256, PROJ_SMEM>>>(0);

    // s2: proj batches 2,3 (needs W)
    cudaStreamWaitEvent(s2, evW, 0);
    proj_tc_kernel<<<pgrid, 256, PROJ_SMEM, s2>>>(2);
    cudaEventRecord(evJoin, s2);

    // s0: attn chunk 0
    attn_mma_kernel<<<agrid, 256, SMEM_BYTES>>>(out, 0);

    // join, then attn chunk 1
    cudaStreamWaitEvent(0, evJoin, 0);
    attn_mma_kernel<<<agrid, 256, SMEM_BYTES>>>(out, NH / 2);
}